// round 7
// baseline (speedup 1.0000x reference)
#include <cuda_runtime.h>
#include <cuda_bf16.h>
#include <math.h>
#include <stdint.h>

// ----------------------------------------------------------------------------
// MemoryNetwork, GB300 sm_103a (PTX target sm_103 => family-portable ISA only)
//
//   M1[d,m,:] = W_topic  @ mems_d[d,m]; M2 likewise (rows 0..95 topic, 96..191 domain)
//   P[b,r]    = feature_b . M[r]   via mma.sync bf16 hi/lo split (3 passes, fp32 acc)
//   fused row-norm + topic softmax + domain softmax epilogue.
//
// R6: R5 double-buffered pipeline with the aregs WAR hazard fixed
//     (stsA consumes aregs BEFORE ldgA overwrites them).
// ----------------------------------------------------------------------------

#define K_DIM   2048
#define TAUF    32.0f
#define NROWS   192
#define KC      64            // bf16 K per chunk
#define NCH     (K_DIM / KC)  // 32

__device__ float                        g_part[4 * NROWS * K_DIM];
__device__ __align__(16) unsigned short g_Bh[NROWS * K_DIM];
__device__ __align__(16) unsigned short g_Bl[NROWS * K_DIM];

// ---------------- helpers ----------------
__device__ __forceinline__ uint32_t smem_u32(const void* p) {
    uint32_t a;
    asm("{ .reg .u64 t; cvta.to.shared.u64 t, %1; cvt.u32.u64 %0, t; }" : "=r"(a) : "l"(p));
    return a;
}
__device__ __forceinline__ unsigned long long dup2(float x) {
    unsigned long long r; asm("mov.b64 %0, {%1, %1};" : "=l"(r) : "f"(x)); return r;
}
__device__ __forceinline__ void ffma2(unsigned long long& d, unsigned long long a,
                                      unsigned long long b) {
    asm("fma.rn.f32x2 %0, %1, %2, %0;" : "+l"(d) : "l"(a), "l"(b));
}
__device__ __forceinline__ float2 unpack2(unsigned long long v) {
    float2 f; asm("mov.b64 {%0, %1}, %2;" : "=f"(f.x), "=f"(f.y) : "l"(v)); return f;
}
__device__ __forceinline__ uint32_t cvt_bf16x2(float lo, float hi) {
    uint32_t r; asm("cvt.rn.bf16x2.f32 %0, %1, %2;" : "=r"(r) : "f"(hi), "f"(lo)); return r;
}
__device__ __forceinline__ void ldsm4(uint32_t* r, uint32_t addr) {
    asm volatile("ldmatrix.sync.aligned.m8n8.x4.shared.b16 {%0,%1,%2,%3}, [%4];"
                 : "=r"(r[0]), "=r"(r[1]), "=r"(r[2]), "=r"(r[3]) : "r"(addr));
}
__device__ __forceinline__ void mma16816(float* d, const uint32_t* a, const uint32_t* b) {
    asm volatile("mma.sync.aligned.m16n8k16.row.col.f32.bf16.bf16.f32 "
                 "{%0,%1,%2,%3}, {%4,%5,%6,%7}, {%8,%9}, {%0,%1,%2,%3};"
                 : "+f"(d[0]), "+f"(d[1]), "+f"(d[2]), "+f"(d[3])
                 : "r"(a[0]), "r"(a[1]), "r"(a[2]), "r"(a[3]), "r"(b[0]), "r"(b[1]));
}
#define CP16(dst, src)  asm volatile("cp.async.cg.shared.global [%0], [%1], 16;" \
                                     :: "r"(dst), "l"(src) : "memory")
#define CP_COMMIT()     asm volatile("cp.async.commit_group;" ::: "memory")
#define CP_WAIT0()      asm volatile("cp.async.wait_group 0;" ::: "memory")

// ----------------------------------------------------------------------------
// A1: split-K partials  g_part[ec][row][k] = sum_{e in chunk} mem[row][e] * W[e][k]
// ----------------------------------------------------------------------------
__global__ void __launch_bounds__(256) build_part_kernel(
    const float* __restrict__ Wt, const float* __restrict__ Wd,
    const float* __restrict__ memtab, const void* __restrict__ catp)
{
    __shared__ __align__(16) float memsm[192][12];

    const int tid = threadIdx.x;
    const int k   = blockIdx.x * 256 + tid;
    const int ry  = blockIdx.y;
    const int ec  = blockIdx.z;
    const int mtx = ry >> 3;
    const int grp = ry & 7;
    const int e0  = ec * 192;

    const int* c32 = (const int*)catp;
    bool is64 = true;
    #pragma unroll
    for (int j = 0; j < 9; j++) if (c32[2 * j + 1] != 0) is64 = false;
    int catv[9];
    #pragma unroll
    for (int j = 0; j < 9; j++)
        catv[j] = is64 ? (int)(((const long long*)catp)[j]) : c32[j];

    for (int idx = tid; idx < 12 * 192; idx += 256) {
        int rr = idx / 192, e = idx % 192;
        int gr = grp * 12 + rr;
        float v = 0.0f;
        if (gr < 90) {
            int d = gr / 10, m = gr % 10;
            v = memtab[(catv[d] * 10 + m) * 768 + e0 + e];
        }
        memsm[e][rr] = v;
    }
    __syncthreads();

    const float* W = mtx ? Wd : Wt;
    unsigned long long acc[6];
    #pragma unroll
    for (int j = 0; j < 6; j++) acc[j] = 0ull;

    #pragma unroll 8
    for (int e = 0; e < 192; e++) {
        unsigned long long wd = dup2(W[(size_t)(e0 + e) * K_DIM + k]);
        const ulonglong2* mr = (const ulonglong2*)(&memsm[e][0]);
        ulonglong2 p0 = mr[0], p1 = mr[1], p2 = mr[2];
        ffma2(acc[0], p0.x, wd); ffma2(acc[1], p0.y, wd);
        ffma2(acc[2], p1.x, wd); ffma2(acc[3], p1.y, wd);
        ffma2(acc[4], p2.x, wd); ffma2(acc[5], p2.y, wd);
    }

    const int base_row = mtx * 96 + grp * 12;
    float* dst = g_part + (size_t)ec * NROWS * K_DIM;
    #pragma unroll
    for (int j = 0; j < 6; j++) {
        float2 v = unpack2(acc[j]);
        dst[(base_row + 2 * j)     * K_DIM + k] = v.x;
        dst[(base_row + 2 * j + 1) * K_DIM + k] = v.y;
    }
}

// ----------------------------------------------------------------------------
// A2: reduce partials; split into bf16 hi (truncated) + lo (rounded)
// ----------------------------------------------------------------------------
__global__ void __launch_bounds__(256) split_B_kernel()
{
    const int row = blockIdx.x;
    #pragma unroll
    for (int i = 0; i < 8; i++) {
        int col = threadIdx.x + 256 * i;
        size_t off = (size_t)row * K_DIM + col;
        float s = g_part[off] + g_part[off + 1ull * NROWS * K_DIM]
                + g_part[off + 2ull * NROWS * K_DIM] + g_part[off + 3ull * NROWS * K_DIM];
        uint32_t u = __float_as_uint(s);
        float hif = __uint_as_float(u & 0xFFFF0000u);
        float lo  = s - hif;
        __nv_bfloat16 lb = __float2bfloat16(lo);
        g_Bh[off] = (unsigned short)(u >> 16);
        g_Bl[off] = *(unsigned short*)&lb;
    }
}

// ----------------------------------------------------------------------------
// Fused mma.sync GEMM + norms + softmaxes (double-buffered pipeline)
// 128 CTAs x 256 threads (8 warps as 4x2); per-CTA tile M=128, N=192
// Per buffer: Ah/Al 128x72 bf16 (18432 B each), Bh/Bl 192x72 bf16 (27648 B each)
// ----------------------------------------------------------------------------
#define LDS_A    72
#define AH_OFF   0
#define AL_OFF   18432
#define BH_OFF   36864
#define BL_OFF   64512
#define BUF_STR  92160
#define CS_LD    194
#define RS_OFF   (2 * BUF_STR)              // 184320 (beyond Cs = 99328)
#define SMEM_TOT (RS_OFF + 128 * 4)         // 184832

__global__ void __launch_bounds__(256, 1) fused_kernel(
    const float* __restrict__ feat, float* __restrict__ out)
{
    extern __shared__ __align__(16) char smem[];
    const uint32_t sbase = smem_u32(smem);
    float* Cs     = (float*)smem;
    float* rowsum = (float*)(smem + RS_OFF);

    const int tid  = threadIdx.x;
    const int lane = tid & 31;
    const int wid  = tid >> 5;
    const int wr   = wid >> 1;      // 0..3 -> 32-row band
    const int wc   = wid & 1;       // 0..1 -> 96-col band
    const int b0   = blockIdx.x * 128;

    if (tid < 128) rowsum[tid] = 0.0f;

    float acc[2][12][4];
    #pragma unroll
    for (int i = 0; i < 2; i++)
        #pragma unroll
        for (int j = 0; j < 12; j++)
            #pragma unroll
            for (int q = 0; q < 4; q++) acc[i][j][q] = 0.0f;

    float ss[4] = {0.f, 0.f, 0.f, 0.f};
    float4 aregs[8];

    auto ldgA = [&](int kc) {
        #pragma unroll
        for (int l = 0; l < 4; l++) {
            int ci = tid + 256 * l, r = ci >> 3, cc = ci & 7;
            const float4* src = (const float4*)(feat + (size_t)(b0 + r) * K_DIM + kc + cc * 8);
            aregs[2 * l]     = src[0];
            aregs[2 * l + 1] = src[1];
        }
    };
    auto stsA = [&](uint32_t bufo) {
        #pragma unroll
        for (int l = 0; l < 4; l++) {
            int ci = tid + 256 * l, r = ci >> 3, cc = ci & 7;
            float4 v0 = aregs[2 * l], v1 = aregs[2 * l + 1];
            float f[8] = {v0.x, v0.y, v0.z, v0.w, v1.x, v1.y, v1.z, v1.w};
            ss[l] += f[0]*f[0] + f[1]*f[1] + f[2]*f[2] + f[3]*f[3]
                   + f[4]*f[4] + f[5]*f[5] + f[6]*f[6] + f[7]*f[7];
            uint32_t hi[4], lo[4];
            #pragma unroll
            for (int p = 0; p < 4; p++) {
                uint32_t u0 = __float_as_uint(f[2*p]), u1 = __float_as_uint(f[2*p+1]);
                hi[p] = (u0 >> 16) | (u1 & 0xFFFF0000u);
                float l0 = f[2*p]   - __uint_as_float(u0 & 0xFFFF0000u);
                float l1 = f[2*p+1] - __uint_as_float(u1 & 0xFFFF0000u);
                lo[p] = cvt_bf16x2(l0, l1);
            }
            uint32_t boff = bufo + (uint32_t)(r * (LDS_A * 2) + cc * 16);
            *(uint4*)(smem + AH_OFF + boff) = make_uint4(hi[0], hi[1], hi[2], hi[3]);
            *(uint4*)(smem + AL_OFF + boff) = make_uint4(lo[0], lo[1], lo[2], lo[3]);
        }
    };
    auto cpB = [&](int kc, uint32_t bufo) {
        #pragma unroll
        for (int l = 0; l < 6; l++) {
            int ci = tid + 256 * l, r = ci >> 3, cc = ci & 7;
            size_t g = (size_t)r * K_DIM + kc + cc * 8;
            uint32_t d = sbase + bufo + (uint32_t)(r * (LDS_A * 2) + cc * 16);
            CP16(d + BH_OFF, g_Bh + g);
            CP16(d + BL_OFF, g_Bl + g);
        }
    };

    // ---- prologue: chunk 0 into buf0, prefetch chunk 1 A ----
    ldgA(0);
    cpB(0, 0);
    CP_COMMIT();
    stsA(0);           // consumes chunk 0 from aregs
    ldgA(KC);          // aregs <- chunk 1 (safe: chunk 0 already stored)
    CP_WAIT0();
    __syncthreads();

    for (int c = 0; c < NCH; c++) {
        const uint32_t rbuf = (uint32_t)(c & 1) * BUF_STR;
        const uint32_t wbuf = rbuf ^ BUF_STR;

        if (c + 1 < NCH) {
            cpB((c + 1) * KC, wbuf);     // async B for next chunk
            CP_COMMIT();
            stsA(wbuf);                  // consume aregs (chunk c+1) FIRST
            if (c + 2 < NCH) ldgA((c + 2) * KC);  // THEN refill aregs; hides under mma
        }

        // ---- warp mma: 3 split passes over chunk c ----
        const int mbase = wr * 32;
        const int nbase = wc * 96;
        #pragma unroll
        for (int k16 = 0; k16 < 4; k16++) {
            const uint32_t akoff = (uint32_t)(k16 * 16 + (lane >> 4) * 8) * 2;
            const uint32_t bkoff = (uint32_t)(k16 * 16 + ((lane >> 3) & 1) * 8) * 2;

            uint32_t ah[2][4], al[2][4];
            #pragma unroll
            for (int mt = 0; mt < 2; mt++) {
                uint32_t rowb = (uint32_t)(mbase + mt * 16 + (lane & 15)) * (LDS_A * 2);
                ldsm4(ah[mt], sbase + rbuf + AH_OFF + rowb + akoff);
                ldsm4(al[mt], sbase + rbuf + AL_OFF + rowb + akoff);
            }
            uint32_t bh[6][4];
            #pragma unroll
            for (int bt = 0; bt < 6; bt++) {
                uint32_t rowb = (uint32_t)(nbase + bt * 16 + (lane & 7) + ((lane >> 4) << 3))
                              * (LDS_A * 2);
                ldsm4(bh[bt], sbase + rbuf + BH_OFF + rowb + bkoff);
            }
            #pragma unroll
            for (int mt = 0; mt < 2; mt++)
                #pragma unroll
                for (int nt = 0; nt < 12; nt++) {
                    mma16816(acc[mt][nt], ah[mt], &bh[nt >> 1][(nt & 1) * 2]);
                    mma16816(acc[mt][nt], al[mt], &bh[nt >> 1][(nt & 1) * 2]);
                }
            uint32_t bl[6][4];
            #pragma unroll
            for (int bt = 0; bt < 6; bt++) {
                uint32_t rowb = (uint32_t)(nbase + bt * 16 + (lane & 7) + ((lane >> 4) << 3))
                              * (LDS_A * 2);
                ldsm4(bl[bt], sbase + rbuf + BL_OFF + rowb + bkoff);
            }
            #pragma unroll
            for (int mt = 0; mt < 2; mt++)
                #pragma unroll
                for (int nt = 0; nt < 12; nt++)
                    mma16816(acc[mt][nt], ah[mt], &bl[nt >> 1][(nt & 1) * 2]);
        }

        if (c + 1 < NCH) {
            CP_WAIT0();
            __syncthreads();
        }
    }
    __syncthreads();   // all mma reads done before Cs overwrites buffers

    // ---- C fragments -> smem ----
    #pragma unroll
    for (int mt = 0; mt < 2; mt++)
        #pragma unroll
        for (int nt = 0; nt < 12; nt++) {
            int row = wr * 32 + mt * 16 + (lane >> 2);
            int col = wc * 96 + nt * 8 + (lane & 3) * 2;
            *(float2*)&Cs[row * CS_LD + col]       = make_float2(acc[mt][nt][0], acc[mt][nt][1]);
            *(float2*)&Cs[(row + 8) * CS_LD + col] = make_float2(acc[mt][nt][2], acc[mt][nt][3]);
        }
    #pragma unroll
    for (int l = 0; l < 4; l++)
        atomicAdd(&rowsum[(tid >> 3) + 32 * l], ss[l]);
    __syncthreads();

    // ---- per-row softmax chain ----
    if (tid < 128) {
        const int    b  = b0 + tid;
        const float  s  = TAUF / fmaxf(sqrtf(rowsum[tid]), 1e-12f);
        const float* cr = Cs + tid * CS_LD;

        float L[9];
        #pragma unroll
        for (int d = 0; d < 9; d++) {
            float mx = -1e30f;
            #pragma unroll
            for (int m = 0; m < 10; m++) mx = fmaxf(mx, cr[d * 10 + m]);
            float se = 0.f, ac = 0.f;
            #pragma unroll
            for (int m = 0; m < 10; m++) {
                float e = expf(s * (cr[d * 10 + m] - mx));
                se += e;
                ac += e * cr[96 + d * 10 + m];
            }
            L[d] = s * ac / se;
        }
        float mx2 = -1e30f;
        #pragma unroll
        for (int d = 0; d < 9; d++) mx2 = fmaxf(mx2, L[d]);
        float ex[9], s2 = 0.f;
        #pragma unroll
        for (int d = 0; d < 9; d++) { ex[d] = expf(L[d] - mx2); s2 += ex[d]; }
        const float inv = 1.0f / s2;
        #pragma unroll
        for (int d = 0; d < 9; d++) out[b * 9 + d] = ex[d] * inv;
    }
}

// ----------------------------------------------------------------------------
extern "C" void kernel_launch(void* const* d_in, const int* in_sizes, int n_in,
                              void* d_out, int out_size)
{
    const float* feature = (const float*)d_in[0];  // (16384, 2048)
    const float* Wt      = (const float*)d_in[1];  // (768, 2048)
    const float* Wd      = (const float*)d_in[2];  // (768, 2048)
    const float* memtab  = (const float*)d_in[3];  // (9, 10, 768)
    const void*  cat     = d_in[4];                // (16384,) int32/int64

    cudaFuncSetAttribute(fused_kernel,
                         cudaFuncAttributeMaxDynamicSharedMemorySize, SMEM_TOT);

    dim3 gA(8, 16, 4);
    build_part_kernel<<<gA, 256>>>(Wt, Wd, memtab, cat);
    split_B_kernel<<<NROWS, 256>>>();
    fused_kernel<<<16384 / 128, 256, SMEM_TOT>>>(feature, (float*)d_out);
}

// round 8
// speedup vs baseline: 1.4148x; 1.4148x over previous
#include <cuda_runtime.h>
#include <cuda_bf16.h>
#include <math.h>
#include <stdint.h>

// ----------------------------------------------------------------------------
// MemoryNetwork, GB300 sm_103a (PTX target sm_103 => family-portable ISA only)
//
//   M1[d,m,:] = W_topic  @ mems_d[d,m]; M2 likewise (rows 0..95 topic, 96..191 domain)
//   P[b,r]    = feature_b . M[r]   via mma.sync bf16 hi/lo split (3 passes, fp32 acc)
//   fused row-norm + topic softmax + domain softmax epilogue.
//
// R7: (a) kernel A merged to ONE kernel (in-block split-K, direct bf16 hi/lo out)
//     (b) fused GEMM: M-tile 64, grid 256, 74KB smem, 2 CTAs/SM for overlap.
// ----------------------------------------------------------------------------

#define K_DIM   2048
#define EMB     768
#define TAUF    32.0f
#define NROWS   192
#define KC      64            // bf16 K per chunk
#define NCH     (K_DIM / KC)  // 32

__device__ __align__(16) unsigned short g_Bh[NROWS * K_DIM];
__device__ __align__(16) unsigned short g_Bl[NROWS * K_DIM];

// ---------------- helpers ----------------
__device__ __forceinline__ uint32_t smem_u32(const void* p) {
    uint32_t a;
    asm("{ .reg .u64 t; cvta.to.shared.u64 t, %1; cvt.u32.u64 %0, t; }" : "=r"(a) : "l"(p));
    return a;
}
__device__ __forceinline__ unsigned long long dup2(float x) {
    unsigned long long r; asm("mov.b64 %0, {%1, %1};" : "=l"(r) : "f"(x)); return r;
}
__device__ __forceinline__ void ffma2(unsigned long long& d, unsigned long long a,
                                      unsigned long long b) {
    asm("fma.rn.f32x2 %0, %1, %2, %0;" : "+l"(d) : "l"(a), "l"(b));
}
__device__ __forceinline__ float2 unpack2(unsigned long long v) {
    float2 f; asm("mov.b64 {%0, %1}, %2;" : "=f"(f.x), "=f"(f.y) : "l"(v)); return f;
}
__device__ __forceinline__ uint32_t cvt_bf16x2(float lo, float hi) {
    uint32_t r; asm("cvt.rn.bf16x2.f32 %0, %1, %2;" : "=r"(r) : "f"(hi), "f"(lo)); return r;
}
__device__ __forceinline__ void ldsm4(uint32_t* r, uint32_t addr) {
    asm volatile("ldmatrix.sync.aligned.m8n8.x4.shared.b16 {%0,%1,%2,%3}, [%4];"
                 : "=r"(r[0]), "=r"(r[1]), "=r"(r[2]), "=r"(r[3]) : "r"(addr));
}
__device__ __forceinline__ void mma16816(float* d, const uint32_t* a, const uint32_t* b) {
    asm volatile("mma.sync.aligned.m16n8k16.row.col.f32.bf16.bf16.f32 "
                 "{%0,%1,%2,%3}, {%4,%5,%6,%7}, {%8,%9}, {%0,%1,%2,%3};"
                 : "+f"(d[0]), "+f"(d[1]), "+f"(d[2]), "+f"(d[3])
                 : "r"(a[0]), "r"(a[1]), "r"(a[2]), "r"(a[3]), "r"(b[0]), "r"(b[1]));
}
#define CP16(dst, src)  asm volatile("cp.async.cg.shared.global [%0], [%1], 16;" \
                                     :: "r"(dst), "l"(src) : "memory")
#define CP_COMMIT()     asm volatile("cp.async.commit_group;" ::: "memory")
#define CP_WAIT0()      asm volatile("cp.async.wait_group 0;" ::: "memory")

// ----------------------------------------------------------------------------
// Kernel A (single launch): M[row][k] = sum_e mem[row][e] * W[e][k], bf16 hi/lo out
// grid (32 kchunk, 16 rowgroup) = 512 blocks, 256 threads = 64 k-cols x 4 e-groups.
// In-block split-K over e via SMEM partials; direct g_Bh/g_Bl stores.
// ----------------------------------------------------------------------------
__global__ void __launch_bounds__(256) build_M_kernel(
    const float* __restrict__ Wt, const float* __restrict__ Wd,
    const float* __restrict__ memtab, const void* __restrict__ catp)
{
    __shared__ __align__(16) float memsm[EMB][12];    // 36864 B; overlaid by partials
    float* part = &memsm[0][0];                       // [4][64][12] after compute

    const int tid = threadIdx.x;
    const int kx  = blockIdx.x;        // 0..31
    const int ry  = blockIdx.y;        // 0..15
    const int mtx = ry >> 3;
    const int grp = ry & 7;
    const int kl  = tid & 63;
    const int k   = kx * 64 + kl;
    const int eg  = tid >> 6;          // 0..3
    const int base_row = mtx * 96 + grp * 12;

    const int* c32 = (const int*)catp;
    bool is64 = true;
    #pragma unroll
    for (int j = 0; j < 9; j++) if (c32[2 * j + 1] != 0) is64 = false;
    int catv[9];
    #pragma unroll
    for (int j = 0; j < 9; j++)
        catv[j] = is64 ? (int)(((const long long*)catp)[j]) : c32[j];

    for (int idx = tid; idx < 12 * EMB; idx += 256) {
        int rr = idx / EMB, e = idx % EMB;
        int gr = grp * 12 + rr;
        float v = 0.0f;
        if (gr < 90) {
            int d = gr / 10, m = gr % 10;
            v = memtab[(catv[d] * 10 + m) * EMB + e];
        }
        memsm[e][rr] = v;
    }
    __syncthreads();

    const float* W = mtx ? Wd : Wt;
    unsigned long long acc[6];
    #pragma unroll
    for (int j = 0; j < 6; j++) acc[j] = 0ull;

    const int e0 = eg * 192;
    #pragma unroll 4
    for (int e = e0; e < e0 + 192; e++) {
        unsigned long long wd = dup2(W[(size_t)e * K_DIM + k]);
        const ulonglong2* mr = (const ulonglong2*)(&memsm[e][0]);
        ulonglong2 p0 = mr[0], p1 = mr[1], p2 = mr[2];
        ffma2(acc[0], p0.x, wd); ffma2(acc[1], p0.y, wd);
        ffma2(acc[2], p1.x, wd); ffma2(acc[3], p1.y, wd);
        ffma2(acc[4], p2.x, wd); ffma2(acc[5], p2.y, wd);
    }

    float vals[12];
    #pragma unroll
    for (int j = 0; j < 6; j++) {
        float2 v = unpack2(acc[j]);
        vals[2 * j] = v.x; vals[2 * j + 1] = v.y;
    }
    __syncthreads();                      // memsm reads complete
    float* pp = part + (eg * 64 + kl) * 12;
    #pragma unroll
    for (int j = 0; j < 12; j++) pp[j] = vals[j];
    __syncthreads();

    // reduce 4 partials, split bf16 hi/lo, store (768 outputs, 3 per thread)
    #pragma unroll
    for (int o = tid; o < 768; o += 256) {
        int okl = o & 63, row = o >> 6;
        float s = part[(0 * 64 + okl) * 12 + row] + part[(1 * 64 + okl) * 12 + row]
                + part[(2 * 64 + okl) * 12 + row] + part[(3 * 64 + okl) * 12 + row];
        uint32_t u = __float_as_uint(s);
        float hif = __uint_as_float(u & 0xFFFF0000u);
        float lo  = s - hif;
        __nv_bfloat16 lb = __float2bfloat16(lo);
        size_t off = (size_t)(base_row + row) * K_DIM + kx * 64 + okl;
        g_Bh[off] = (unsigned short)(u >> 16);
        g_Bl[off] = *(unsigned short*)&lb;
    }
}

// ----------------------------------------------------------------------------
// Fused mma.sync GEMM + norms + softmaxes
// grid 256 CTAs x 256 threads (8 warps as 2x4); per-CTA tile M=64, N=192
// SMEM (single buffer, 74KB => 2 CTAs/SM): Ah/Al 64x72 bf16, Bh/Bl 192x72 bf16
// ----------------------------------------------------------------------------
#define BM       64
#define LDS_A    72
#define AH_OFF   0
#define AL_OFF   9216
#define BH_OFF   18432
#define BL_OFF   46080
#define CS_LD    194
#define RS_OFF   73728                       // end of tiles (also > Cs = 64*194*4)
#define SMEM_TOT (RS_OFF + BM * 4)           // 73984

__global__ void __launch_bounds__(256, 2) fused_kernel(
    const float* __restrict__ feat, float* __restrict__ out)
{
    extern __shared__ __align__(16) char smem[];
    const uint32_t sbase = smem_u32(smem);
    float* Cs     = (float*)smem;
    float* rowsum = (float*)(smem + RS_OFF);

    const int tid  = threadIdx.x;
    const int lane = tid & 31;
    const int wid  = tid >> 5;
    const int wr   = wid >> 2;      // 0..1 -> 32-row band
    const int wc   = wid & 3;       // 0..3 -> 48-col band
    const int b0   = blockIdx.x * BM;

    if (tid < BM) rowsum[tid] = 0.0f;

    float acc[2][6][4];
    #pragma unroll
    for (int i = 0; i < 2; i++)
        #pragma unroll
        for (int j = 0; j < 6; j++)
            #pragma unroll
            for (int q = 0; q < 4; q++) acc[i][j][q] = 0.0f;

    float ss[2] = {0.f, 0.f};
    float4 aregs[4];

    auto ldgA = [&](int kc) {
        #pragma unroll
        for (int l = 0; l < 2; l++) {
            int ci = tid + 256 * l, r = ci >> 3, cc = ci & 7;
            const float4* src = (const float4*)(feat + (size_t)(b0 + r) * K_DIM + kc + cc * 8);
            aregs[2 * l]     = src[0];
            aregs[2 * l + 1] = src[1];
        }
    };
    auto stsA = [&]() {
        #pragma unroll
        for (int l = 0; l < 2; l++) {
            int ci = tid + 256 * l, r = ci >> 3, cc = ci & 7;
            float4 v0 = aregs[2 * l], v1 = aregs[2 * l + 1];
            float f[8] = {v0.x, v0.y, v0.z, v0.w, v1.x, v1.y, v1.z, v1.w};
            ss[l] += f[0]*f[0] + f[1]*f[1] + f[2]*f[2] + f[3]*f[3]
                   + f[4]*f[4] + f[5]*f[5] + f[6]*f[6] + f[7]*f[7];
            uint32_t hi[4], lo[4];
            #pragma unroll
            for (int p = 0; p < 4; p++) {
                uint32_t u0 = __float_as_uint(f[2*p]), u1 = __float_as_uint(f[2*p+1]);
                hi[p] = (u0 >> 16) | (u1 & 0xFFFF0000u);
                float l0 = f[2*p]   - __uint_as_float(u0 & 0xFFFF0000u);
                float l1 = f[2*p+1] - __uint_as_float(u1 & 0xFFFF0000u);
                lo[p] = cvt_bf16x2(l0, l1);
            }
            uint32_t boff = (uint32_t)(r * (LDS_A * 2) + cc * 16);
            *(uint4*)(smem + AH_OFF + boff) = make_uint4(hi[0], hi[1], hi[2], hi[3]);
            *(uint4*)(smem + AL_OFF + boff) = make_uint4(lo[0], lo[1], lo[2], lo[3]);
        }
    };
    auto cpB = [&](int kc) {
        #pragma unroll
        for (int l = 0; l < 6; l++) {
            int ci = tid + 256 * l, r = ci >> 3, cc = ci & 7;
            size_t g = (size_t)r * K_DIM + kc + cc * 8;
            uint32_t d = sbase + (uint32_t)(r * (LDS_A * 2) + cc * 16);
            CP16(d + BH_OFF, g_Bh + g);
            CP16(d + BL_OFF, g_Bl + g);
        }
    };

    ldgA(0);

    for (int c = 0; c < NCH; c++) {
        cpB(c * KC);                          // async B -> smem (L2 resident)
        CP_COMMIT();
        stsA();                               // consume aregs (chunk c)
        if (c + 1 < NCH) ldgA((c + 1) * KC);  // refill; latency hides under mma
        CP_WAIT0();
        __syncthreads();

        // ---- warp mma: 3 split passes over chunk c ----
        const int mbase = wr * 32;
        const int nbase = wc * 48;
        #pragma unroll
        for (int k16 = 0; k16 < 4; k16++) {
            const uint32_t akoff = (uint32_t)(k16 * 16 + (lane >> 4) * 8) * 2;
            const uint32_t bkoff = (uint32_t)(k16 * 16 + ((lane >> 3) & 1) * 8) * 2;

            uint32_t ah[2][4], al[2][4];
            #pragma unroll
            for (int mt = 0; mt < 2; mt++) {
                uint32_t rowb = (uint32_t)(mbase + mt * 16 + (lane & 15)) * (LDS_A * 2);
                ldsm4(ah[mt], sbase + AH_OFF + rowb + akoff);
                ldsm4(al[mt], sbase + AL_OFF + rowb + akoff);
            }
            uint32_t bh[3][4];
            #pragma unroll
            for (int bt = 0; bt < 3; bt++) {
                uint32_t rowb = (uint32_t)(nbase + bt * 16 + (lane & 7) + ((lane >> 4) << 3))
                              * (LDS_A * 2);
                ldsm4(bh[bt], sbase + BH_OFF + rowb + bkoff);
            }
            #pragma unroll
            for (int mt = 0; mt < 2; mt++)
                #pragma unroll
                for (int nt = 0; nt < 6; nt++) {
                    mma16816(acc[mt][nt], ah[mt], &bh[nt >> 1][(nt & 1) * 2]);
                    mma16816(acc[mt][nt], al[mt], &bh[nt >> 1][(nt & 1) * 2]);
                }
            uint32_t bl[3][4];
            #pragma unroll
            for (int bt = 0; bt < 3; bt++) {
                uint32_t rowb = (uint32_t)(nbase + bt * 16 + (lane & 7) + ((lane >> 4) << 3))
                              * (LDS_A * 2);
                ldsm4(bl[bt], sbase + BL_OFF + rowb + bkoff);
            }
            #pragma unroll
            for (int mt = 0; mt < 2; mt++)
                #pragma unroll
                for (int nt = 0; nt < 6; nt++)
                    mma16816(acc[mt][nt], ah[mt], &bl[nt >> 1][(nt & 1) * 2]);
        }
        __syncthreads();                      // B/A reads done before next overwrite
    }

    // ---- C fragments -> smem ----
    #pragma unroll
    for (int mt = 0; mt < 2; mt++)
        #pragma unroll
        for (int nt = 0; nt < 6; nt++) {
            int row = wr * 32 + mt * 16 + (lane >> 2);
            int col = wc * 48 + nt * 8 + (lane & 3) * 2;
            *(float2*)&Cs[row * CS_LD + col]       = make_float2(acc[mt][nt][0], acc[mt][nt][1]);
            *(float2*)&Cs[(row + 8) * CS_LD + col] = make_float2(acc[mt][nt][2], acc[mt][nt][3]);
        }
    #pragma unroll
    for (int l = 0; l < 2; l++)
        atomicAdd(&rowsum[(tid >> 3) + 32 * l], ss[l]);
    __syncthreads();

    // ---- per-row softmax chain ----
    if (tid < BM) {
        const int    b  = b0 + tid;
        const float  s  = TAUF / fmaxf(sqrtf(rowsum[tid]), 1e-12f);
        const float* cr = Cs + tid * CS_LD;

        float L[9];
        #pragma unroll
        for (int d = 0; d < 9; d++) {
            float mx = -1e30f;
            #pragma unroll
            for (int m = 0; m < 10; m++) mx = fmaxf(mx, cr[d * 10 + m]);
            float se = 0.f, ac = 0.f;
            #pragma unroll
            for (int m = 0; m < 10; m++) {
                float e = expf(s * (cr[d * 10 + m] - mx));
                se += e;
                ac += e * cr[96 + d * 10 + m];
            }
            L[d] = s * ac / se;
        }
        float mx2 = -1e30f;
        #pragma unroll
        for (int d = 0; d < 9; d++) mx2 = fmaxf(mx2, L[d]);
        float ex[9], s2 = 0.f;
        #pragma unroll
        for (int d = 0; d < 9; d++) { ex[d] = expf(L[d] - mx2); s2 += ex[d]; }
        const float inv = 1.0f / s2;
        #pragma unroll
        for (int d = 0; d < 9; d++) out[b * 9 + d] = ex[d] * inv;
    }
}

// ----------------------------------------------------------------------------
extern "C" void kernel_launch(void* const* d_in, const int* in_sizes, int n_in,
                              void* d_out, int out_size)
{
    const float* feature = (const float*)d_in[0];  // (16384, 2048)
    const float* Wt      = (const float*)d_in[1];  // (768, 2048)
    const float* Wd      = (const float*)d_in[2];  // (768, 2048)
    const float* memtab  = (const float*)d_in[3];  // (9, 10, 768)
    const void*  cat     = d_in[4];                // (16384,) int32/int64

    cudaFuncSetAttribute(fused_kernel,
                         cudaFuncAttributeMaxDynamicSharedMemorySize, SMEM_TOT);

    dim3 gA(32, 16);
    build_M_kernel<<<gA, 256>>>(Wt, Wd, memtab, cat);
    fused_kernel<<<16384 / BM, 256, SMEM_TOT>>>(feature, (float*)d_out);
}